// round 12
// baseline (speedup 1.0000x reference)
#include <cuda_runtime.h>

#define N_NODES 50000
#define N_EDGES 800000
#define D_FEAT  64
#define WARPS_PER_BLOCK 8
#define ROWS_PER_BLOCK (WARPS_PER_BLOCK * 2)   // half-warp per row

// Precomputed CSR row pointers.
__device__ int g_row_ptr[N_NODES + 1];

// Prep: O(E) scatter build of row_ptr from sorted row_idx. That's all.
__global__ __launch_bounds__(256)
void prep_kernel(const int* __restrict__ row_idx) {
    const int t = blockIdx.x * blockDim.x + threadIdx.x;
    if (t > N_EDGES) return;
    if (t == 0) {
        const int r1 = __ldg(row_idx + 0);
        for (int r = 0; r <= r1; r++) g_row_ptr[r] = 0;
    } else {
        const int r0 = __ldg(row_idx + t - 1);
        const int r1 = (t < N_EDGES) ? __ldg(row_idx + t) : N_NODES;
        for (int r = r0 + 1; r <= r1; r++) g_row_ptr[r] = t;
    }
}

// Packed f32x2 helpers.
__device__ __forceinline__ unsigned long long pk2(float lo, float hi) {
    unsigned long long r;
    asm("mov.b64 %0, {%1, %2};" : "=l"(r) : "f"(lo), "f"(hi));
    return r;
}
__device__ __forceinline__ void ffma2(unsigned long long& acc,
                                      unsigned long long x,
                                      unsigned long long v) {
    asm("fma.rn.f32x2 %0, %1, %2, %3;" : "=l"(acc) : "l"(x), "l"(v), "l"(acc));
}
__device__ __forceinline__ float2 unpk2(unsigned long long p) {
    float2 f;
    asm("mov.b64 {%0, %1}, %2;" : "=f"(f.x), "=f"(f.y) : "l"(p));
    return f;
}

// SpMM: HALF-warp per row. 16 lanes x float4 = full 256B fp32 row; each lane
// owns dims [4q..4q+3] -> lane-local accumulators, no cross-lane reduction,
// direct coalesced float4 store. fp32 gathers: no convert/pack overhead.
// Main loop: 4 edges/iter, 4 independent gathers in flight.
__global__ __launch_bounds__(WARPS_PER_BLOCK * 32)
void gcn_spmm_kernel(const int* __restrict__ col_idx,
                     const float* __restrict__ vals,
                     const float* __restrict__ embeds,
                     float* __restrict__ out) {
    const int tid  = threadIdx.x;
    const int lane = tid & 31;
    const int q    = lane & 15;                      // float4 slice of the row
    const int row  = blockIdx.x * ROWS_PER_BLOCK + (tid >> 4);

    const int start = __ldg(&g_row_ptr[row]);
    const int end   = __ldg(&g_row_ptr[row + 1]);

    const float4* __restrict__ emb4 = reinterpret_cast<const float4*>(embeds);

    unsigned long long A0 = 0ull, A1 = 0ull;        // 4 fp32 accumulators

    int e = start;
    // Main: unguarded 4-edge chunks, 4 independent gathers in flight.
    for (; e + 4 <= end; e += 4) {
        const int c0 = __ldg(col_idx + e);
        const int c1 = __ldg(col_idx + e + 1);
        const int c2 = __ldg(col_idx + e + 2);
        const int c3 = __ldg(col_idx + e + 3);
        const float4 x0 = __ldg(emb4 + (size_t)c0 * 16 + q);
        const float4 x1 = __ldg(emb4 + (size_t)c1 * 16 + q);
        const float4 x2 = __ldg(emb4 + (size_t)c2 * 16 + q);
        const float4 x3 = __ldg(emb4 + (size_t)c3 * 16 + q);
        const float v0 = __ldg(vals + e);
        const float v1 = __ldg(vals + e + 1);
        const float v2 = __ldg(vals + e + 2);
        const float v3 = __ldg(vals + e + 3);

        unsigned long long vv;
        vv = pk2(v0, v0);
        ffma2(A0, pk2(x0.x, x0.y), vv);
        ffma2(A1, pk2(x0.z, x0.w), vv);
        vv = pk2(v1, v1);
        ffma2(A0, pk2(x1.x, x1.y), vv);
        ffma2(A1, pk2(x1.z, x1.w), vv);
        vv = pk2(v2, v2);
        ffma2(A0, pk2(x2.x, x2.y), vv);
        ffma2(A1, pk2(x2.z, x2.w), vv);
        vv = pk2(v3, v3);
        ffma2(A0, pk2(x3.x, x3.y), vv);
        ffma2(A1, pk2(x3.z, x3.w), vv);
    }
    // Tail: <= 3 edges.
    for (; e < end; e++) {
        const int c0 = __ldg(col_idx + e);
        const float4 x0 = __ldg(emb4 + (size_t)c0 * 16 + q);
        const float v0 = __ldg(vals + e);
        const unsigned long long vv = pk2(v0, v0);
        ffma2(A0, pk2(x0.x, x0.y), vv);
        ffma2(A1, pk2(x0.z, x0.w), vv);
    }

    // Direct store: lane q writes floats [4q..4q+3]. 16 lanes = full 256B row.
    const float2 u0 = unpk2(A0), u1 = unpk2(A1);
    reinterpret_cast<float4*>(out)[(size_t)row * 16 + q] =
        make_float4(u0.x, u0.y, u1.x, u1.y);
}

extern "C" void kernel_launch(void* const* d_in, const int* in_sizes, int n_in,
                              void* d_out, int out_size) {
    const int*   row_idx = (const int*)  d_in[0];
    const int*   col_idx = (const int*)  d_in[1];
    const float* vals    = (const float*)d_in[2];
    const float* embeds  = (const float*)d_in[3];
    float*       out     = (float*)d_out;

    prep_kernel<<<(N_EDGES + 1 + 255) / 256, 256>>>(row_idx);

    const int blocks = N_NODES / ROWS_PER_BLOCK;   // 50000/16 = 3125 exactly
    gcn_spmm_kernel<<<blocks, WARPS_PER_BLOCK * 32>>>(col_idx, vals, embeds,
                                                      out);
}

// round 13
// speedup vs baseline: 1.0014x; 1.0014x over previous
#include <cuda_runtime.h>
#include <cuda_fp16.h>

#define N_NODES 50000
#define N_EDGES 800000
#define D_FEAT  64
#define WARPS_PER_BLOCK 8
#define ROWS_PER_BLOCK (WARPS_PER_BLOCK * 4)   // quarter-warp per row
#define CONV_THREADS (N_NODES * D_FEAT / 8)    // 400000

// Precomputed CSR row pointers.
__device__ int g_row_ptr[N_NODES + 1];
// fp16 copy of embeds: one 128B cache line per row. 6.4MB, L2-resident.
__device__ __half2 g_emb_h[N_NODES * D_FEAT / 2];

// Fused prep: O(E) scatter row_ptr build + fp32->fp16 embed convert.
__global__ __launch_bounds__(256)
void prep_kernel(const int* __restrict__ row_idx,
                 const float* __restrict__ embeds) {
    const int t = blockIdx.x * blockDim.x + threadIdx.x;

    if (t <= N_EDGES) {
        if (t == 0) {
            const int r1 = __ldg(row_idx + 0);
            for (int r = 0; r <= r1; r++) g_row_ptr[r] = 0;
        } else {
            const int r0 = __ldg(row_idx + t - 1);
            const int r1 = (t < N_EDGES) ? __ldg(row_idx + t) : N_NODES;
            for (int r = r0 + 1; r <= r1; r++) g_row_ptr[r] = t;
        }
    }

    if (t < CONV_THREADS) {
        const float4* e4 = reinterpret_cast<const float4*>(embeds);
        const float4 a = __ldg(e4 + 2 * t);
        const float4 b = __ldg(e4 + 2 * t + 1);
        __half2* dst = g_emb_h + 4 * t;
        dst[0] = __float22half2_rn(make_float2(a.x, a.y));
        dst[1] = __float22half2_rn(make_float2(a.z, a.w));
        dst[2] = __float22half2_rn(make_float2(b.x, b.y));
        dst[3] = __float22half2_rn(make_float2(b.z, b.w));
    }
}

// Packed f32x2 helpers.
__device__ __forceinline__ unsigned long long pk2(float lo, float hi) {
    unsigned long long r;
    asm("mov.b64 %0, {%1, %2};" : "=l"(r) : "f"(lo), "f"(hi));
    return r;
}
__device__ __forceinline__ void ffma2(unsigned long long& acc,
                                      unsigned long long x,
                                      unsigned long long v) {
    asm("fma.rn.f32x2 %0, %1, %2, %3;" : "=l"(acc) : "l"(x), "l"(v), "l"(acc));
}
__device__ __forceinline__ float2 unpk2(unsigned long long p) {
    float2 f;
    asm("mov.b64 {%0, %1}, %2;" : "=f"(f.x), "=f"(f.y) : "l"(p));
    return f;
}

// Accumulate one fp16 embed row slice (uint4 = 8 halves) times v.
__device__ __forceinline__ void acc_edge(unsigned long long& A0,
                                         unsigned long long& A1,
                                         unsigned long long& A2,
                                         unsigned long long& A3,
                                         uint4 x, float v) {
    const unsigned long long vv = pk2(v, v);
    float2 f;
    f = __half22float2(*reinterpret_cast<const __half2*>(&x.x));
    ffma2(A0, pk2(f.x, f.y), vv);
    f = __half22float2(*reinterpret_cast<const __half2*>(&x.y));
    ffma2(A1, pk2(f.x, f.y), vv);
    f = __half22float2(*reinterpret_cast<const __half2*>(&x.z));
    ffma2(A2, pk2(f.x, f.y), vv);
    f = __half22float2(*reinterpret_cast<const __half2*>(&x.w));
    ffma2(A3, pk2(f.x, f.y), vv);
}

// Kernel B: QUARTER-warp per row (8 lanes x uint4 = full 128B fp16 row = ONE
// cache line per gather). Lane-local accumulators, no cross-lane reduction.
// Metadata via vector loads: one int4 + one float4 per 4 edges.
__global__ __launch_bounds__(WARPS_PER_BLOCK * 32)
void gcn_spmm_kernel(const int* __restrict__ col_idx,
                     const float* __restrict__ vals,
                     float* __restrict__ out) {
    const int tid  = threadIdx.x;
    const int lane = tid & 31;
    const int q    = lane & 7;                       // dim slice
    const int row  = blockIdx.x * ROWS_PER_BLOCK + (tid >> 3);
    if (row >= N_NODES) return;

    const int start = __ldg(&g_row_ptr[row]);
    const int end   = __ldg(&g_row_ptr[row + 1]);

    const uint4* __restrict__ emb16 = reinterpret_cast<const uint4*>(g_emb_h);

    unsigned long long A0 = 0ull, A1 = 0ull, A2 = 0ull, A3 = 0ull;

    int e = start;

    // Prologue: scalar edges until e is 4-aligned (<=3 iterations).
    const int aligned = min(end, (start + 3) & ~3);
    for (; e < aligned; e++) {
        const int c0 = __ldg(col_idx + e);
        const uint4 x0 = __ldg(emb16 + (size_t)c0 * 8 + q);
        const float v0 = __ldg(vals + e);
        acc_edge(A0, A1, A2, A3, x0, v0);
    }

    // Main: 4 edges/iter; metadata via ONE int4 + ONE float4 load; 4
    // independent gathers in flight (each = 1 cache line).
    for (; e + 4 <= end; e += 4) {
        const int4   c4 = __ldg(reinterpret_cast<const int4*>(col_idx + e));
        const float4 v4 = __ldg(reinterpret_cast<const float4*>(vals + e));
        const uint4 x0 = __ldg(emb16 + (size_t)c4.x * 8 + q);
        const uint4 x1 = __ldg(emb16 + (size_t)c4.y * 8 + q);
        const uint4 x2 = __ldg(emb16 + (size_t)c4.z * 8 + q);
        const uint4 x3 = __ldg(emb16 + (size_t)c4.w * 8 + q);

        acc_edge(A0, A1, A2, A3, x0, v4.x);
        acc_edge(A0, A1, A2, A3, x1, v4.y);
        acc_edge(A0, A1, A2, A3, x2, v4.z);
        acc_edge(A0, A1, A2, A3, x3, v4.w);
    }

    // Tail: <= 3 edges.
    for (; e < end; e++) {
        const int c0 = __ldg(col_idx + e);
        const uint4 x0 = __ldg(emb16 + (size_t)c0 * 8 + q);
        const float v0 = __ldg(vals + e);
        acc_edge(A0, A1, A2, A3, x0, v0);
    }

    // Direct store: lane q writes floats [8q..8q+7] of the row. No shuffles.
    const float2 u0 = unpk2(A0), u1 = unpk2(A1);
    const float2 u2 = unpk2(A2), u3 = unpk2(A3);
    float4* o4 = reinterpret_cast<float4*>(out + (size_t)row * D_FEAT + q * 8);
    o4[0] = make_float4(u0.x, u0.y, u1.x, u1.y);
    o4[1] = make_float4(u2.x, u2.y, u3.x, u3.y);
}

extern "C" void kernel_launch(void* const* d_in, const int* in_sizes, int n_in,
                              void* d_out, int out_size) {
    const int*   row_idx = (const int*)  d_in[0];
    const int*   col_idx = (const int*)  d_in[1];
    const float* vals    = (const float*)d_in[2];
    const float* embeds  = (const float*)d_in[3];
    float*       out     = (float*)d_out;

    prep_kernel<<<(N_EDGES + 1 + 255) / 256, 256>>>(row_idx, embeds);

    const int blocks = (N_NODES + ROWS_PER_BLOCK - 1) / ROWS_PER_BLOCK; // 1563
    gcn_spmm_kernel<<<blocks, WARPS_PER_BLOCK * 32>>>(col_idx, vals, out);
}